// round 15
// baseline (speedup 1.0000x reference)
#include <cuda_runtime.h>
#include <cuda_bf16.h>

// ---------------------------------------------------------------------------
// TrajEmbedding: GATConv (8 heads x 8 ch, self-loops, segment softmax) + ReLU
// + padded trajectory gather.
//
// Round 15: half-split head-major row layout for g_xw/g_emb so every LDG.128
// in the aggregation covers a FULL 128B line (2 wf/edge instead of 4), and
// each lane owns exactly one head (single a_src scalar + single exp).
//
//   permuted row: [h0c0..3, h1c0..3, ..., h7c0..3 | h0c4..7, ..., h7c4..7]
//   lane t (=lane&7) loads float4 at idx t (first half) and 8+t (second).
//   k_gather un-permutes with pq = (q&1) ? 8+(q>>1) : (q>>1).
//
//   k_prep      : index dtype sniff + zero bucket cursors
//   k_xw        : xw = x@W (smem W), head dots via shuffles, permuted store
//   k_scatter   : g_srcs[d*CAP + cur[d]++] = s   (int atomics only)
//   k_aggregate : one warp per node, warp-uniform control flow, register
//                 softmax-weighted accumulation (max-shift folded out:
//                 logits O(1), unnormalized exp exact to ~1e-7 rel)
//   k_gather    : out[b,l,:] = emb[traj[b,l],:] * (l < len[b])
//   k_tail      : optional seq_lengths append depending on out_size
// ---------------------------------------------------------------------------

#define NN      100000
#define NE      1600000
#define FEAT    64
#define HEADS   8
#define BATCH   64
#define MAXLEN  2048
#define CAP     64                           // deg ~ Poisson(16); P(>64)~1e-24
#define EMB_ELEMS (BATCH * MAXLEN * FEAT)   // 8,388,608

// Scratch (device globals: allocations are forbidden)
__device__ float g_xw[(size_t)NN * FEAT];       // 25.6 MB (permuted rows)
__device__ float g_asrc[(size_t)NN * HEADS];    //  3.2 MB
__device__ float g_adst[(size_t)NN * HEADS];    //  3.2 MB
__device__ float g_emb[(size_t)NN * FEAT];      // 25.6 MB (permuted rows)
__device__ int   g_cur[NN];                     //  0.4 MB
__device__ int   g_srcs[(size_t)NN * CAP];      // 25.6 MB
__device__ int   g_idx64;                       // 1 if indices are int64

__device__ __forceinline__ int idx_at(const void* p, int i, int is64) {
    long long v = is64 ? ((const long long*)p)[i] : (long long)((const int*)p)[i];
    // clamp defensively: a mis-detected dtype shows up as rel_err, not an IMA
    if (v < 0) v = 0;
    if (v >= NN) v = NN - 1;
    return (int)v;
}

// ---------------------------------------------------------------------------
// Prep: detect index width (int64 node ids < 1e5 have zero high words) and
// zero the bucket cursors.
// ---------------------------------------------------------------------------
__global__ void k_prep(const void* __restrict__ ei) {
    int i = blockIdx.x * blockDim.x + threadIdx.x;
    if (i == 0) {
        const int2* p = (const int2*)ei;
        int all_hi_zero = 1;
#pragma unroll
        for (int j = 0; j < 16; j++)
            if (p[j].y != 0) all_hi_zero = 0;
        g_idx64 = all_hi_zero;
    }
    if (i < NN) g_cur[i] = 0;
}

// ---------------------------------------------------------------------------
// K1: xw = x @ W, a_src/a_dst head dots. Stores rows in the half-split
// head-major permutation.
// ---------------------------------------------------------------------------
__global__ __launch_bounds__(256) void k_xw(const float* __restrict__ x,
                                            const float* __restrict__ W,
                                            const float* __restrict__ att_s,
                                            const float* __restrict__ att_d) {
    __shared__ float sW[64 * 64];
    __shared__ float sas[64];
    __shared__ float sad[64];
    __shared__ float sx[4 * 64];

    for (int i = threadIdx.x; i < 64 * 64; i += 256) sW[i] = W[i];
    if (threadIdx.x < 64) {
        sas[threadIdx.x] = att_s[threadIdx.x];
        sad[threadIdx.x] = att_d[threadIdx.x];
    }
    __syncthreads();

    const int k = threadIdx.x & 63;   // output channel (standard order)
    const int r = threadIdx.x >> 6;   // row sub-index 0..3
    // permuted position of channel k: head h=k>>3, i=k&7
    const int ph = k >> 3, pi = k & 7;
    const int pos = (pi < 4) ? (ph * 4 + pi) : (32 + ph * 4 + (pi - 4));

    for (int base = blockIdx.x * 4; base < NN; base += gridDim.x * 4) {
        int row = base + r;
        sx[threadIdx.x] = (row < NN) ? x[(size_t)row * FEAT + k] : 0.f;
        __syncthreads();

        float acc = 0.f;
#pragma unroll
        for (int f = 0; f < 64; f++)
            acc = fmaf(sx[r * 64 + f], sW[f * 64 + k], acc);

        float vs = acc * sas[k];
        float vd = acc * sad[k];
#pragma unroll
        for (int off = 4; off; off >>= 1) {
            vs += __shfl_down_sync(0xffffffffu, vs, off);
            vd += __shfl_down_sync(0xffffffffu, vd, off);
        }

        if (row < NN) {
            g_xw[(size_t)row * FEAT + pos] = acc;   // permuted store, same lines
            if ((k & 7) == 0) {
                int h = k >> 3;
                g_asrc[(size_t)row * HEADS + h] = vs;
                g_adst[(size_t)row * HEADS + h] = vd;
            }
        }
        __syncthreads();
    }
}

// ---------------------------------------------------------------------------
// Scatter src ids into fixed-capacity dst buckets (no scan needed).
// ---------------------------------------------------------------------------
__global__ __launch_bounds__(256) void k_scatter(const void* __restrict__ ei) {
    int i = blockIdx.x * blockDim.x + threadIdx.x;
    if (i >= NE) return;
    const int is64 = g_idx64;
    int s = idx_at(ei, i, is64);
    int d = idx_at(ei, NE + i, is64);
    int pos = atomicAdd(&g_cur[d], 1);
    if (pos < CAP)  // never fires on valid data; guards OOB under bad inputs
        g_srcs[(size_t)d * CAP + pos] = s;
}

// ---------------------------------------------------------------------------
// K2: per-node aggregation. One warp per node; lane = (edge_slot<<3) | head.
// With the permuted row layout, lane t loads head t's 8 channels via two
// FULL-LINE float4 loads (idx t and 8+t). All control flow warp-uniform;
// per-slot validity predicated into the exp weight (shfl always collective).
// ---------------------------------------------------------------------------
__global__ __launch_bounds__(256) void k_aggregate(const float* __restrict__ bias) {
    int w = (blockIdx.x * blockDim.x + threadIdx.x) >> 5;   // node id
    if (w >= NN) return;
    const int lane = threadIdx.x & 31;
    const int sub  = lane >> 3;    // edge slot 0..3
    const int t    = lane & 7;     // head

    const int d = w;
    const float adst_t = g_adst[(size_t)d * HEADS + t];

    float acc0, acc1, acc2, acc3, acc4, acc5, acc6, acc7, den;

    // self loop: computed on all lanes, weight zeroed outside slot 0
    {
        const float4* v = reinterpret_cast<const float4*>(g_xw + (size_t)d * FEAT);
        float4 v0 = v[t];        // head t channels 0..3 (first 128B line)
        float4 v1 = v[8 + t];    // head t channels 4..7 (second line)
        float z = g_asrc[(size_t)d * HEADS + t] + adst_t;
        float ex = (sub == 0) ? __expf(fmaxf(z, 0.2f * z)) : 0.f;
        acc0 = ex * v0.x; acc1 = ex * v0.y; acc2 = ex * v0.z; acc3 = ex * v0.w;
        acc4 = ex * v1.x; acc5 = ex * v1.y; acc6 = ex * v1.z; acc7 = ex * v1.w;
        den = ex;
    }

    int deg = g_cur[d];           // warp-uniform
    if (deg > CAP) deg = CAP;
    const size_t beg = (size_t)d * CAP;

    for (int chunk = 0; chunk < deg; chunk += 32) {       // uniform
        int nc = deg - chunk; if (nc > 32) nc = 32;       // uniform
        // one coalesced load covers up to 32 edge src-ids; invalid lanes -> 0
        int sid = (lane < nc) ? g_srcs[beg + chunk + lane] : 0;

        // uniform trip count (jb depends only on nc); edges jb+sub (A) and
        // jb+4+sub (B) per slot, validity predicated into the weight.
        for (int jb = 0; jb < nc; jb += 8) {              // uniform
            int jA = jb + sub;
            int jB = jb + 4 + sub;
            int sA = __shfl_sync(0xffffffffu, sid, jA & 31);
            int sB = __shfl_sync(0xffffffffu, sid, jB & 31);
            const float4* vA = reinterpret_cast<const float4*>(g_xw + (size_t)sA * FEAT);
            const float4* vB = reinterpret_cast<const float4*>(g_xw + (size_t)sB * FEAT);
            float4 a0 = vA[t],     a1 = vA[8 + t];
            float4 b0 = vB[t],     b1 = vB[8 + t];
            float aa = g_asrc[(size_t)sA * HEADS + t];
            float ab = g_asrc[(size_t)sB * HEADS + t];
            float za = aa + adst_t;
            float zb = ab + adst_t;
            float exa = (jA < nc) ? __expf(fmaxf(za, 0.2f * za)) : 0.f;
            float exb = (jB < nc) ? __expf(fmaxf(zb, 0.2f * zb)) : 0.f;
            acc0 = fmaf(exa, a0.x, acc0); acc1 = fmaf(exa, a0.y, acc1);
            acc2 = fmaf(exa, a0.z, acc2); acc3 = fmaf(exa, a0.w, acc3);
            acc4 = fmaf(exa, a1.x, acc4); acc5 = fmaf(exa, a1.y, acc5);
            acc6 = fmaf(exa, a1.z, acc6); acc7 = fmaf(exa, a1.w, acc7);
            den += exa;
            acc0 = fmaf(exb, b0.x, acc0); acc1 = fmaf(exb, b0.y, acc1);
            acc2 = fmaf(exb, b0.z, acc2); acc3 = fmaf(exb, b0.w, acc3);
            acc4 = fmaf(exb, b1.x, acc4); acc5 = fmaf(exb, b1.y, acc5);
            acc6 = fmaf(exb, b1.z, acc6); acc7 = fmaf(exb, b1.w, acc7);
            den += exb;
        }
    }

    // reduce across the 4 edge slots (uniform, all lanes participate)
#pragma unroll
    for (int o = 8; o <= 16; o <<= 1) {
        den  += __shfl_xor_sync(0xffffffffu, den,  o);
        acc0 += __shfl_xor_sync(0xffffffffu, acc0, o);
        acc1 += __shfl_xor_sync(0xffffffffu, acc1, o);
        acc2 += __shfl_xor_sync(0xffffffffu, acc2, o);
        acc3 += __shfl_xor_sync(0xffffffffu, acc3, o);
        acc4 += __shfl_xor_sync(0xffffffffu, acc4, o);
        acc5 += __shfl_xor_sync(0xffffffffu, acc5, o);
        acc6 += __shfl_xor_sync(0xffffffffu, acc6, o);
        acc7 += __shfl_xor_sync(0xffffffffu, acc7, o);
    }

    if (sub == 0) {
        float inv = 1.0f / den;
        // bias for head t, channels 0..7 (standard layout in input)
        const float4* bp = reinterpret_cast<const float4*>(bias + t * 8);
        float4 b0 = bp[0], b1 = bp[1];
        float4 o0, o1;
        o0.x = fmaxf(fmaf(acc0, inv, b0.x), 0.f);
        o0.y = fmaxf(fmaf(acc1, inv, b0.y), 0.f);
        o0.z = fmaxf(fmaf(acc2, inv, b0.z), 0.f);
        o0.w = fmaxf(fmaf(acc3, inv, b0.w), 0.f);
        o1.x = fmaxf(fmaf(acc4, inv, b1.x), 0.f);
        o1.y = fmaxf(fmaf(acc5, inv, b1.y), 0.f);
        o1.z = fmaxf(fmaf(acc6, inv, b1.z), 0.f);
        o1.w = fmaxf(fmaf(acc7, inv, b1.w), 0.f);
        // store in PERMUTED layout: two full-line 128B stores per node
        float4* op = reinterpret_cast<float4*>(g_emb + (size_t)d * FEAT);
        op[t]     = o0;   // head t ch0..3 -> first line
        op[8 + t] = o1;   // head t ch4..7 -> second line
    }
}

// ---------------------------------------------------------------------------
// K4: padded trajectory gather; 16 threads per (b,l) position. Un-permutes
// the emb row layout via index remap (free).
// ---------------------------------------------------------------------------
__global__ __launch_bounds__(256) void k_gather(const void* __restrict__ traj,
                                                const void* __restrict__ lens,
                                                float* __restrict__ out) {
    int i = blockIdx.x * blockDim.x + threadIdx.x;  // output float4 index
    const int TOT = EMB_ELEMS / 4;  // 2,097,152
    if (i >= TOT) return;
    const int is64 = g_idx64;
    int pos = i >> 4;          // b*MAXLEN + l
    int q = i & 15;            // output float4 within row (standard layout)
    int b = pos >> 11;
    int l = pos & (MAXLEN - 1);
    // standard out float4 q = head q>>1, channels (q&1)*4.. -> permuted idx:
    int pq = (q & 1) ? (8 + (q >> 1)) : (q >> 1);
    long long len = is64 ? ((const long long*)lens)[b] : (long long)((const int*)lens)[b];
    float4 v = make_float4(0.f, 0.f, 0.f, 0.f);
    if ((long long)l < len) {
        int node = idx_at(traj, pos, is64);
        v = reinterpret_cast<const float4*>(g_emb)[(size_t)node * 16 + pq];
    }
    reinterpret_cast<float4*>(out)[i] = v;
}

// Optional second output (seq_lengths tail), layout-dependent.
__global__ void k_tail_f32(float* __restrict__ out, const void* __restrict__ lens) {
    int b = threadIdx.x;
    if (b < BATCH) {
        long long v = g_idx64 ? ((const long long*)lens)[b]
                              : (long long)((const int*)lens)[b];
        out[EMB_ELEMS + b] = (float)v;
    }
}
__global__ void k_tail_i64(long long* __restrict__ outt, const void* __restrict__ lens) {
    int b = threadIdx.x;
    if (b < BATCH) {
        long long v = g_idx64 ? ((const long long*)lens)[b]
                              : (long long)((const int*)lens)[b];
        outt[b] = v;
    }
}

// ---------------------------------------------------------------------------
extern "C" void kernel_launch(void* const* d_in, const int* in_sizes, int n_in,
                              void* d_out, int out_size) {
    // Map inputs by element count (robust to metadata reordering).
    const float* x = 0; const float* W = 0;
    const float* att_s = 0; const float* att_d = 0; const float* bias = 0;
    const void* ei = 0; const void* traj = 0; const void* lens = 0;
    int small_seen = 0;
    for (int i = 0; i < n_in; i++) {
        switch (in_sizes[i]) {
            case 6400000: x    = (const float*)d_in[i]; break;
            case 4096:    W    = (const float*)d_in[i]; break;
            case 3200000: ei   = d_in[i]; break;
            case 131072:  traj = d_in[i]; break;
            case 64:
                if      (small_seen == 0) att_s = (const float*)d_in[i];
                else if (small_seen == 1) att_d = (const float*)d_in[i];
                else if (small_seen == 2) bias  = (const float*)d_in[i];
                else                      lens  = d_in[i];
                small_seen++;
                break;
            default: break;
        }
    }
    if (!x || !W || !ei || !traj || !lens || !att_s || !att_d || !bias) {
        x     = (const float*)d_in[0];
        W     = (const float*)d_in[1];
        att_s = (const float*)d_in[2];
        att_d = (const float*)d_in[3];
        bias  = (const float*)d_in[4];
        ei    = d_in[5];
        traj  = d_in[6];
        lens  = d_in[7];
    }
    float* out = (float*)d_out;

    k_prep<<<(NN + 1023) / 1024, 1024>>>(ei);
    k_xw<<<2048, 256>>>(x, W, att_s, att_d);

    k_scatter<<<(NE + 255) / 256, 256>>>(ei);
    k_aggregate<<<(NN * 32 + 255) / 256, 256>>>(bias);
    k_gather<<<(EMB_ELEMS / 4 + 255) / 256, 256>>>(traj, lens, out);

    int extra = out_size - EMB_ELEMS;
    if (extra >= 2 * BATCH) {
        k_tail_i64<<<1, 64>>>((long long*)(out + EMB_ELEMS), lens);
    } else if (extra >= BATCH) {
        k_tail_f32<<<1, 64>>>(out, lens);
    }
}

// round 17
// speedup vs baseline: 1.3205x; 1.3205x over previous
#include <cuda_runtime.h>
#include <cuda_bf16.h>

// ---------------------------------------------------------------------------
// TrajEmbedding: GATConv (8 heads x 8 ch, self-loops, segment softmax) + ReLU
// + padded trajectory gather.
//
// Round 17 = Round 16 resubmitted unchanged (prior bench was a container
// flake; source audited for hangs/collective-divergence/alignment — clean).
//
// f32x2 packed math:
//  - k_xw: W pre-packed along the reduction dim in smem (LDS.64, conflict
//    free), 4 rows/thread register blocking, fma.rn.f32x2 -> 3.2x fewer LDS
//    instructions (the old version was LDS-issue bound at ~50us).
//  - k_aggregate: packed f32x2 accumulators (4 FFMA2/edge instead of 8 FFMA)
//    in the issue-bound hot loop. Row layout stays half-split head-major:
//    [h0c0..3,...,h7c0..3 | h0c4..7,...,h7c4..7]; lane t reads float4 idx t
//    and 8+t (full 128B lines). Warp-uniform control flow throughout.
//  - max-shift folded out of softmax: logits O(1), exact to ~1e-7 rel.
// ---------------------------------------------------------------------------

#define NN      100000
#define NE      1600000
#define FEAT    64
#define HEADS   8
#define BATCH   64
#define MAXLEN  2048
#define CAP     64                           // deg ~ Poisson(16); P(>64)~1e-24
#define EMB_ELEMS (BATCH * MAXLEN * FEAT)   // 8,388,608

// Scratch (device globals: allocations are forbidden)
__device__ float g_xw[(size_t)NN * FEAT];       // 25.6 MB (permuted rows)
__device__ float g_asrc[(size_t)NN * HEADS];    //  3.2 MB
__device__ float g_adst[(size_t)NN * HEADS];    //  3.2 MB
__device__ float g_emb[(size_t)NN * FEAT];      // 25.6 MB (permuted rows)
__device__ int   g_cur[NN];                     //  0.4 MB
__device__ int   g_srcs[(size_t)NN * CAP];      // 25.6 MB
__device__ int   g_idx64;                       // 1 if indices are int64

typedef unsigned long long ull;

__device__ __forceinline__ ull pack2(float lo, float hi) {
    ull r; asm("mov.b64 %0, {%1, %2};" : "=l"(r) : "f"(lo), "f"(hi)); return r;
}
__device__ __forceinline__ float2 unpack2(ull v) {
    float lo, hi; asm("mov.b64 {%0, %1}, %2;" : "=f"(lo), "=f"(hi) : "l"(v));
    return make_float2(lo, hi);
}
__device__ __forceinline__ ull fma2(ull a, ull b, ull c) {
    ull r; asm("fma.rn.f32x2 %0, %1, %2, %3;" : "=l"(r) : "l"(a), "l"(b), "l"(c));
    return r;
}
__device__ __forceinline__ ull add2(ull a, ull b) {
    ull r; asm("add.rn.f32x2 %0, %1, %2;" : "=l"(r) : "l"(a), "l"(b));
    return r;
}

__device__ __forceinline__ int idx_at(const void* p, int i, int is64) {
    long long v = is64 ? ((const long long*)p)[i] : (long long)((const int*)p)[i];
    if (v < 0) v = 0;
    if (v >= NN) v = NN - 1;   // clamp: bad inputs -> rel_err, not IMA
    return (int)v;
}

// ---------------------------------------------------------------------------
// Prep: detect index width (int64 node ids < 1e5 have zero high words) and
// zero the bucket cursors.
// ---------------------------------------------------------------------------
__global__ void k_prep(const void* __restrict__ ei) {
    int i = blockIdx.x * blockDim.x + threadIdx.x;
    if (i == 0) {
        const int2* p = (const int2*)ei;
        int all_hi_zero = 1;
#pragma unroll
        for (int j = 0; j < 16; j++)
            if (p[j].y != 0) all_hi_zero = 0;
        g_idx64 = all_hi_zero;
    }
    if (i < NN) g_cur[i] = 0;
}

// ---------------------------------------------------------------------------
// K1: xw = x @ W with packed f32x2 math. 256 threads = 64 cols x 4 groups;
// each thread computes 4 rows (g, g+4, g+8, g+12) of one column -> one W
// LDS.64 feeds 4 FFMA2. Stores rows in the half-split head-major permutation.
// ---------------------------------------------------------------------------
__global__ __launch_bounds__(256) void k_xw(const float* __restrict__ x,
                                            const float* __restrict__ W,
                                            const float* __restrict__ att_s,
                                            const float* __restrict__ att_d) {
    __shared__ ull   sWp[32 * 64];   // [f2][k]: (W[2f2][k], W[2f2+1][k]) 16KB
    __shared__ float sx[16 * 64];    // 16 rows of x                       4KB
    __shared__ float sas[64];
    __shared__ float sad[64];

    for (int idx = threadIdx.x; idx < 32 * 64; idx += 256) {
        int f2 = idx >> 6, kk = idx & 63;
        sWp[idx] = pack2(W[(2 * f2) * 64 + kk], W[(2 * f2 + 1) * 64 + kk]);
    }
    if (threadIdx.x < 64) {
        sas[threadIdx.x] = att_s[threadIdx.x];
        sad[threadIdx.x] = att_d[threadIdx.x];
    }
    __syncthreads();

    const int k = threadIdx.x & 63;   // output channel (standard order)
    const int g = threadIdx.x >> 6;   // row group 0..3
    const int ph = k >> 3, pi = k & 7;
    const int pos = (pi < 4) ? (ph * 4 + pi) : (32 + ph * 4 + (pi - 4));
    const float ask = sas[k], adk = sad[k];

    for (int base = blockIdx.x * 16; base < NN; base += gridDim.x * 16) {
        // cooperative load of 16 x-rows (float4-coalesced)
        {
            int row = threadIdx.x >> 4;   // 0..15
            int f4  = threadIdx.x & 15;
            int r_  = base + row;
            float4 val = (r_ < NN) ? reinterpret_cast<const float4*>(x)[(size_t)r_ * 16 + f4]
                                   : make_float4(0.f, 0.f, 0.f, 0.f);
            reinterpret_cast<float4*>(sx)[row * 16 + f4] = val;
        }
        __syncthreads();

        ull acc[4] = {0ull, 0ull, 0ull, 0ull};   // (0.0,0.0) packed
        const ull* xr0 = reinterpret_cast<const ull*>(sx + (g)      * 64);
        const ull* xr1 = reinterpret_cast<const ull*>(sx + (g + 4)  * 64);
        const ull* xr2 = reinterpret_cast<const ull*>(sx + (g + 8)  * 64);
        const ull* xr3 = reinterpret_cast<const ull*>(sx + (g + 12) * 64);
#pragma unroll
        for (int f2 = 0; f2 < 32; f2++) {
            ull w2 = sWp[f2 * 64 + k];
            acc[0] = fma2(xr0[f2], w2, acc[0]);
            acc[1] = fma2(xr1[f2], w2, acc[1]);
            acc[2] = fma2(xr2[f2], w2, acc[2]);
            acc[3] = fma2(xr3[f2], w2, acc[3]);
        }

#pragma unroll
        for (int j = 0; j < 4; j++) {
            int row = base + g + 4 * j;
            float2 p = unpack2(acc[j]);
            float a = p.x + p.y;

            float vs = a * ask;
            float vd = a * adk;
#pragma unroll
            for (int off = 4; off; off >>= 1) {
                vs += __shfl_down_sync(0xffffffffu, vs, off);
                vd += __shfl_down_sync(0xffffffffu, vd, off);
            }

            if (row < NN) {
                g_xw[(size_t)row * FEAT + pos] = a;   // permuted store
                if ((k & 7) == 0) {
                    int h = k >> 3;
                    g_asrc[(size_t)row * HEADS + h] = vs;
                    g_adst[(size_t)row * HEADS + h] = vd;
                }
            }
        }
        __syncthreads();
    }
}

// ---------------------------------------------------------------------------
// Scatter src ids into fixed-capacity dst buckets (no scan needed).
// ---------------------------------------------------------------------------
__global__ __launch_bounds__(256) void k_scatter(const void* __restrict__ ei) {
    int i = blockIdx.x * blockDim.x + threadIdx.x;
    if (i >= NE) return;
    const int is64 = g_idx64;
    int s = idx_at(ei, i, is64);
    int d = idx_at(ei, NE + i, is64);
    int pos = atomicAdd(&g_cur[d], 1);
    if (pos < CAP)  // never fires on valid data; guards OOB under bad inputs
        g_srcs[(size_t)d * CAP + pos] = s;
}

// ---------------------------------------------------------------------------
// K2: per-node aggregation. One warp per node; lane = (edge_slot<<3) | head.
// Packed f32x2 accumulators: 4 FFMA2 per edge. Permuted layout -> lane t
// loads head t's 8 channels via two full-line LDG.128 (ulonglong2). All
// control flow warp-uniform; per-slot validity predicated into the weight.
// ---------------------------------------------------------------------------
__global__ __launch_bounds__(256) void k_aggregate(const float* __restrict__ bias) {
    int w = (blockIdx.x * blockDim.x + threadIdx.x) >> 5;   // node id
    if (w >= NN) return;
    const int lane = threadIdx.x & 31;
    const int sub  = lane >> 3;    // edge slot 0..3
    const int t    = lane & 7;     // head

    const int d = w;
    const float adst_t = g_adst[(size_t)d * HEADS + t];

    ull acc[4];
    float den;

    // self loop: computed on all lanes, weight zeroed outside slot 0
    {
        const ulonglong2* v = reinterpret_cast<const ulonglong2*>(g_xw + (size_t)d * FEAT);
        ulonglong2 v0 = v[t];        // head t ch 0..3 (first 128B line)
        ulonglong2 v1 = v[8 + t];    // head t ch 4..7 (second line)
        float z = g_asrc[(size_t)d * HEADS + t] + adst_t;
        float ex = (sub == 0) ? __expf(fmaxf(z, 0.2f * z)) : 0.f;
        ull ex2 = pack2(ex, ex);
        acc[0] = fma2(ex2, v0.x, 0ull);
        acc[1] = fma2(ex2, v0.y, 0ull);
        acc[2] = fma2(ex2, v1.x, 0ull);
        acc[3] = fma2(ex2, v1.y, 0ull);
        den = ex;
    }

    int deg = g_cur[d];           // warp-uniform
    if (deg > CAP) deg = CAP;
    const size_t beg = (size_t)d * CAP;

    for (int chunk = 0; chunk < deg; chunk += 32) {       // uniform
        int nc = deg - chunk; if (nc > 32) nc = 32;       // uniform
        int sid = (lane < nc) ? g_srcs[beg + chunk + lane] : 0;

        for (int jb = 0; jb < nc; jb += 8) {              // uniform trip count
            int jA = jb + sub;
            int jB = jb + 4 + sub;
            int sA = __shfl_sync(0xffffffffu, sid, jA & 31);
            int sB = __shfl_sync(0xffffffffu, sid, jB & 31);
            const ulonglong2* vA = reinterpret_cast<const ulonglong2*>(g_xw + (size_t)sA * FEAT);
            const ulonglong2* vB = reinterpret_cast<const ulonglong2*>(g_xw + (size_t)sB * FEAT);
            ulonglong2 a0 = vA[t], a1 = vA[8 + t];
            ulonglong2 b0 = vB[t], b1 = vB[8 + t];
            float aa = g_asrc[(size_t)sA * HEADS + t];
            float ab = g_asrc[(size_t)sB * HEADS + t];
            float za = aa + adst_t;
            float zb = ab + adst_t;
            float exa = (jA < nc) ? __expf(fmaxf(za, 0.2f * za)) : 0.f;
            float exb = (jB < nc) ? __expf(fmaxf(zb, 0.2f * zb)) : 0.f;
            ull exa2 = pack2(exa, exa);
            ull exb2 = pack2(exb, exb);
            acc[0] = fma2(exa2, a0.x, acc[0]);
            acc[1] = fma2(exa2, a0.y, acc[1]);
            acc[2] = fma2(exa2, a1.x, acc[2]);
            acc[3] = fma2(exa2, a1.y, acc[3]);
            den += exa;
            acc[0] = fma2(exb2, b0.x, acc[0]);
            acc[1] = fma2(exb2, b0.y, acc[1]);
            acc[2] = fma2(exb2, b1.x, acc[2]);
            acc[3] = fma2(exb2, b1.y, acc[3]);
            den += exb;
        }
    }

    // reduce across the 4 edge slots (uniform, all lanes participate)
#pragma unroll
    for (int o = 8; o <= 16; o <<= 1) {
        den += __shfl_xor_sync(0xffffffffu, den, o);
#pragma unroll
        for (int i = 0; i < 4; i++)
            acc[i] = add2(acc[i], __shfl_xor_sync(0xffffffffu, acc[i], o));
    }

    if (sub == 0) {
        float inv = 1.0f / den;
        const float4* bp = reinterpret_cast<const float4*>(bias + t * 8);
        float4 b0 = bp[0], b1 = bp[1];
        float2 p0 = unpack2(acc[0]);
        float2 p1 = unpack2(acc[1]);
        float2 p2 = unpack2(acc[2]);
        float2 p3 = unpack2(acc[3]);
        float4 o0, o1;
        o0.x = fmaxf(fmaf(p0.x, inv, b0.x), 0.f);
        o0.y = fmaxf(fmaf(p0.y, inv, b0.y), 0.f);
        o0.z = fmaxf(fmaf(p1.x, inv, b0.z), 0.f);
        o0.w = fmaxf(fmaf(p1.y, inv, b0.w), 0.f);
        o1.x = fmaxf(fmaf(p2.x, inv, b1.x), 0.f);
        o1.y = fmaxf(fmaf(p2.y, inv, b1.y), 0.f);
        o1.z = fmaxf(fmaf(p3.x, inv, b1.z), 0.f);
        o1.w = fmaxf(fmaf(p3.y, inv, b1.w), 0.f);
        // store in PERMUTED layout: two full-line stores per node
        float4* op = reinterpret_cast<float4*>(g_emb + (size_t)d * FEAT);
        op[t]     = o0;   // head t ch0..3 -> first line
        op[8 + t] = o1;   // head t ch4..7 -> second line
    }
}

// ---------------------------------------------------------------------------
// K4: padded trajectory gather; 16 threads per (b,l) position. Un-permutes
// the emb row layout via index remap (free).
// ---------------------------------------------------------------------------
__global__ __launch_bounds__(256) void k_gather(const void* __restrict__ traj,
                                                const void* __restrict__ lens,
                                                float* __restrict__ out) {
    int i = blockIdx.x * blockDim.x + threadIdx.x;  // output float4 index
    const int TOT = EMB_ELEMS / 4;  // 2,097,152
    if (i >= TOT) return;
    const int is64 = g_idx64;
    int pos = i >> 4;          // b*MAXLEN + l
    int q = i & 15;            // output float4 within row (standard layout)
    int b = pos >> 11;
    int l = pos & (MAXLEN - 1);
    int pq = (q & 1) ? (8 + (q >> 1)) : (q >> 1);   // permuted index
    long long len = is64 ? ((const long long*)lens)[b] : (long long)((const int*)lens)[b];
    float4 v = make_float4(0.f, 0.f, 0.f, 0.f);
    if ((long long)l < len) {
        int node = idx_at(traj, pos, is64);
        v = reinterpret_cast<const float4*>(g_emb)[(size_t)node * 16 + pq];
    }
    reinterpret_cast<float4*>(out)[i] = v;
}

// Optional second output (seq_lengths tail), layout-dependent.
__global__ void k_tail_f32(float* __restrict__ out, const void* __restrict__ lens) {
    int b = threadIdx.x;
    if (b < BATCH) {
        long long v = g_idx64 ? ((const long long*)lens)[b]
                              : (long long)((const int*)lens)[b];
        out[EMB_ELEMS + b] = (float)v;
    }
}
__global__ void k_tail_i64(long long* __restrict__ outt, const void* __restrict__ lens) {
    int b = threadIdx.x;
    if (b < BATCH) {
        long long v = g_idx64 ? ((const long long*)lens)[b]
                              : (long long)((const int*)lens)[b];
        outt[b] = v;
    }
}

// ---------------------------------------------------------------------------
extern "C" void kernel_launch(void* const* d_in, const int* in_sizes, int n_in,
                              void* d_out, int out_size) {
    // Map inputs by element count (robust to metadata reordering).
    const float* x = 0; const float* W = 0;
    const float* att_s = 0; const float* att_d = 0; const float* bias = 0;
    const void* ei = 0; const void* traj = 0; const void* lens = 0;
    int small_seen = 0;
    for (int i = 0; i < n_in; i++) {
        switch (in_sizes[i]) {
            case 6400000: x    = (const float*)d_in[i]; break;
            case 4096:    W    = (const float*)d_in[i]; break;
            case 3200000: ei   = d_in[i]; break;
            case 131072:  traj = d_in[i]; break;
            case 64:
                if      (small_seen == 0) att_s = (const float*)d_in[i];
                else if (small_seen == 1) att_d = (const float*)d_in[i];
                else if (small_seen == 2) bias  = (const float*)d_in[i];
                else                      lens  = d_in[i];
                small_seen++;
                break;
            default: break;
        }
    }
    if (!x || !W || !ei || !traj || !lens || !att_s || !att_d || !bias) {
        x     = (const float*)d_in[0];
        W     = (const float*)d_in[1];
        att_s = (const float*)d_in[2];
        att_d = (const float*)d_in[3];
        bias  = (const float*)d_in[4];
        ei    = d_in[5];
        traj  = d_in[6];
        lens  = d_in[7];
    }
    float* out = (float*)d_out;

    k_prep<<<(NN + 1023) / 1024, 1024>>>(ei);
    k_xw<<<1024, 256>>>(x, W, att_s, att_d);

    k_scatter<<<(NE + 255) / 256, 256>>>(ei);
    k_aggregate<<<(NN * 32 + 255) / 256, 256>>>(bias);
    k_gather<<<(EMB_ELEMS / 4 + 255) / 256, 256>>>(traj, lens, out);

    int extra = out_size - EMB_ELEMS;
    if (extra >= 2 * BATCH) {
        k_tail_i64<<<1, 64>>>((long long*)(out + EMB_ELEMS), lens);
    } else if (extra >= BATCH) {
        k_tail_f32<<<1, 64>>>(out, lens);
    }
}